// round 16
// baseline (speedup 1.0000x reference)
#include <cuda_runtime.h>
#include <cuda_bf16.h>
#include <math.h>

// Problem constants
#define BB   4
#define TT   2048
#define DD   1024
#define HH   16
#define HD   64
#define LAT  128
#define ROPE 32
#define ROWS (BB*TT)          // 8192
#define EPSV 1e-6f
#define KVSPLIT 4

// Scratch (tf32-bit tensors stored as float bit-patterns)
__device__ float g_xb  [ROWS * DD];          // x as tf32 bits
__device__ float g_qr  [ROWS * HH * ROPE];   // tf32 bits, pre-scaled by 0.125
__device__ float g_kv  [ROWS * LAT];         // tf32 bits
__device__ float g_kvp [KVSPLIT * ROWS * LAT];
__device__ float g_k   [ROWS * HH * ROPE];   // tf32 bits
__device__ float g_v   [ROWS * HH * ROPE];   // tf32 bits
__device__ float g_att [ROWS * HH * ROPE];   // tf32 bits
__device__ float g_wop [HH * ROPE * DD];     // tf32 bits
__device__ float g_wqb [DD * DD];            // tf32 bits
__device__ float g_wkvb[DD * LAT];           // tf32 bits
__device__ float g_wkb [LAT * HH * ROPE];    // tf32 bits
__device__ float g_wvb [LAT * HH * ROPE];    // tf32 bits

// ---------------------------------------------------------------------------
__device__ __forceinline__ unsigned f2tf(float f) {
    unsigned u;
    asm("cvt.rna.tf32.f32 %0, %1;" : "=r"(u) : "f"(f));
    return u;
}
__device__ __forceinline__ float f2tf_f(float f) { return __uint_as_float(f2tf(f)); }

__device__ __forceinline__ void mma_tf32(
    float* c, unsigned a0, unsigned a1, unsigned a2, unsigned a3,
    unsigned b0, unsigned b1)
{
    asm volatile(
        "mma.sync.aligned.m16n8k8.row.col.f32.tf32.tf32.f32 "
        "{%0,%1,%2,%3}, {%4,%5,%6,%7}, {%8,%9}, {%0,%1,%2,%3};"
        : "+f"(c[0]), "+f"(c[1]), "+f"(c[2]), "+f"(c[3])
        : "r"(a0), "r"(a1), "r"(a2), "r"(a3), "r"(b0), "r"(b1));
}

#define CP_ASYNC16(dst_u32, src_ptr) \
    asm volatile("cp.async.cg.shared.global [%0], [%1], 16;" \
                 :: "r"(dst_u32), "l"(src_ptr))
#define CP_COMMIT() asm volatile("cp.async.commit_group;")
#define CP_WAIT2()  asm volatile("cp.async.wait_group 2;")

// ---------------------------------------------------------------------------
// elementwise fp32 -> tf32-bits
// ---------------------------------------------------------------------------
__global__ void conv_tf32(const float4* __restrict__ in, float4* __restrict__ out, int n4)
{
    int i = blockIdx.x * blockDim.x + threadIdx.x;
    if (i >= n4) return;
    float4 v = in[i];
    out[i] = make_float4(f2tf_f(v.x), f2tf_f(v.y), f2tf_f(v.z), f2tf_f(v.w));
}

// ---------------------------------------------------------------------------
// 4-stage cp.async pipelined TF32 GEMM. 128x128 CTA tile, BK=16, 256 thr,
// 8 warps (2x4), warp tile 64x32. A and B BOTH pre-converted tf32 bits.
// Dynamic smem: 4 x (As[128][20] + Bs[16][136]) = 75776 B, 2 CTAs/SM.
// MODE 0: fp32 store
// MODE 2: fused Q-RMSNorm*0.125 -> packed qr (ld 512), tf32 store
// MODE 3: split-K fp32 partials
// ---------------------------------------------------------------------------
#define ASTRIDE 20
#define BSTRIDE 136
#define ABUF (128*ASTRIDE)
#define BBUF (16*BSTRIDE)
#define NSTAGE 4
#define GEMM_SMEM (NSTAGE*(ABUF + BBUF) * 4)

template<int MODE>
__global__ __launch_bounds__(256, 2) void gemm_ca(
    int M, int N, int K, int lda,
    const float* __restrict__ A, const float* __restrict__ B,
    float* __restrict__ C, const float* __restrict__ gvec)
{
    extern __shared__ unsigned dsm[];
    unsigned* Asb = dsm;                     // NSTAGE x 128 x 20
    unsigned* Bsb = dsm + NSTAGE * ABUF;     // NSTAGE x 16 x 136
    __shared__ float ssbuf[128][4];          // MODE 2 only

    const int tid  = threadIdx.x;
    const int lane = tid & 31;
    const int warp = tid >> 5;
    const int g    = lane >> 2;
    const int t4   = lane & 3;
    const int wr   = warp >> 2;
    const int wc   = warp & 3;

    const int bM = blockIdx.y * 128;
    const int bN = (MODE == 3) ? 0 : blockIdx.x * 128;

    const float* Ap = A;
    const float* Bp = B;
    float*       Cp = C;
    if (MODE == 3) {
        Ap += (size_t)blockIdx.x * K;
        Bp += (size_t)blockIdx.x * K * N;
        Cp += (size_t)blockIdx.x * M * N;
    }

    const float* Ab = Ap + (size_t)bM * lda;
    const float* Bb = Bp + bN;

    const int aRow = tid >> 2;
    const int aCol = (tid & 3) * 4;
    const int bRow = tid >> 5;
    const int bCol = (tid & 31) * 4;

    unsigned sbase;
    asm("{ .reg .u64 t; cvta.to.shared.u64 t, %1; cvt.u32.u64 %0, t; }"
        : "=r"(sbase) : "l"(dsm));
    const unsigned dA0 = sbase + (aRow * ASTRIDE + aCol) * 4;
    const unsigned dA1 = dA0 + 64 * ASTRIDE * 4;
    const unsigned dB0 = sbase + (NSTAGE * ABUF + bRow * BSTRIDE + bCol) * 4;
    const unsigned dB1 = dB0 + 8 * BSTRIDE * 4;

    auto issue = [&](int buf, int k0) {
        const float* ga0 = &Ab[(size_t)aRow * lda + k0 + aCol];
        const float* gb0 = &Bb[(size_t)(k0 + bRow) * N + bCol];
        unsigned offA = buf * ABUF * 4;
        unsigned offB = buf * BBUF * 4;
        CP_ASYNC16(dA0 + offA, ga0);
        CP_ASYNC16(dA1 + offA, ga0 + (size_t)64 * lda);
        CP_ASYNC16(dB0 + offB, gb0);
        CP_ASYNC16(dB1 + offB, gb0 + (size_t)8 * N);
        CP_COMMIT();
    };

    float acc[4][4][4];
    #pragma unroll
    for (int i = 0; i < 4; i++)
        #pragma unroll
        for (int j = 0; j < 4; j++)
            #pragma unroll
            for (int c = 0; c < 4; c++) acc[i][j][c] = 0.f;

    const int nIter = K >> 4;   // >= 8 for all shapes here
    issue(0, 0);
    issue(1, 16);
    issue(2, 32);

    int buf = 0;
    for (int it = 0; it < nIter; it++) {
        CP_WAIT2();            // <=2 groups pending -> group `it` retired
        __syncthreads();

        if (it + 3 < nIter)
            issue((buf + 3) & 3, (it + 3) << 4);

        const unsigned* As = Asb + buf * ABUF;
        const unsigned* Bs = Bsb + buf * BBUF;

        #pragma unroll
        for (int kb = 0; kb < 2; kb++) {
            const int kk = kb * 8;
            unsigned a[4][4], b[4][2];
            #pragma unroll
            for (int mi = 0; mi < 4; mi++) {
                int row = wr * 64 + mi * 16 + g;
                a[mi][0] = As[row * ASTRIDE + kk + t4];
                a[mi][1] = As[(row + 8) * ASTRIDE + kk + t4];
                a[mi][2] = As[row * ASTRIDE + kk + t4 + 4];
                a[mi][3] = As[(row + 8) * ASTRIDE + kk + t4 + 4];
            }
            #pragma unroll
            for (int ni = 0; ni < 4; ni++) {
                int col = wc * 32 + ni * 8 + g;
                b[ni][0] = Bs[(kk + t4) * BSTRIDE + col];
                b[ni][1] = Bs[(kk + t4 + 4) * BSTRIDE + col];
            }
            #pragma unroll
            for (int mi = 0; mi < 4; mi++)
                #pragma unroll
                for (int ni = 0; ni < 4; ni++)
                    mma_tf32(acc[mi][ni], a[mi][0], a[mi][1], a[mi][2], a[mi][3],
                             b[ni][0], b[ni][1]);
        }
        buf = (buf + 1) & 3;
    }

    if (MODE == 0 || MODE == 3) {
        #pragma unroll
        for (int mi = 0; mi < 4; mi++) {
            #pragma unroll
            for (int ni = 0; ni < 4; ni++) {
                int row = bM + wr * 64 + mi * 16 + g;
                int col = bN + wc * 32 + ni * 8 + 2 * t4;
                *(float2*)&Cp[(size_t)row * N + col] =
                    make_float2(acc[mi][ni][0], acc[mi][ni][1]);
                *(float2*)&Cp[(size_t)(row + 8) * N + col] =
                    make_float2(acc[mi][ni][2], acc[mi][ni][3]);
            }
        }
    } else {   // MODE 2: Q head = 64 cols = warp pair; smem partial sums
        #pragma unroll
        for (int mi = 0; mi < 4; mi++) {
            float ss0 = 0.f, ss1 = 0.f;
            #pragma unroll
            for (int ni = 0; ni < 4; ni++) {
                ss0 += acc[mi][ni][0]*acc[mi][ni][0] + acc[mi][ni][1]*acc[mi][ni][1];
                ss1 += acc[mi][ni][2]*acc[mi][ni][2] + acc[mi][ni][3]*acc[mi][ni][3];
            }
            ss0 += __shfl_xor_sync(0xffffffffu, ss0, 1);
            ss0 += __shfl_xor_sync(0xffffffffu, ss0, 2);
            ss1 += __shfl_xor_sync(0xffffffffu, ss1, 1);
            ss1 += __shfl_xor_sync(0xffffffffu, ss1, 2);
            if (t4 == 0) {
                int lr = wr * 64 + mi * 16 + g;
                ssbuf[lr][wc]     = ss0;
                ssbuf[lr + 8][wc] = ss1;
            }
        }
        __syncthreads();
        if ((wc & 1) == 0) {
            #pragma unroll
            for (int mi = 0; mi < 4; mi++) {
                int lr = wr * 64 + mi * 16 + g;
                float t0 = ssbuf[lr][wc] + ssbuf[lr][wc ^ 1];
                float t1 = ssbuf[lr + 8][wc] + ssbuf[lr + 8][wc ^ 1];
                float rinv0 = 0.125f * rsqrtf(t0 * (1.0f / HD) + EPSV);
                float rinv1 = 0.125f * rsqrtf(t1 * (1.0f / HD) + EPSV);
                int row = bM + lr;
                #pragma unroll
                for (int ni = 0; ni < 4; ni++) {
                    int d  = ni * 8 + 2 * t4;
                    int cg = bN + wc * 32 + d;
                    int qc = (cg >> 6) * 32 + d;
                    float g0 = gvec[d], g1 = gvec[d + 1];
                    *(float2*)&Cp[(size_t)row * 512 + qc] =
                        make_float2(f2tf_f(acc[mi][ni][0] * rinv0 * g0),
                                    f2tf_f(acc[mi][ni][1] * rinv0 * g1));
                    *(float2*)&Cp[(size_t)(row + 8) * 512 + qc] =
                        make_float2(f2tf_f(acc[mi][ni][2] * rinv1 * g0),
                                    f2tf_f(acc[mi][ni][3] * rinv1 * g1));
                }
            }
        }
    }
}

// ---------------------------------------------------------------------------
// Merged k+v GEMM: grid (8, 64). x-tiles 0..3 -> k (fused K-RMSNorm, tf32),
// x-tiles 4..7 -> v (plain tf32 store). A = kv (tf32 bits), N = 512, K = 128.
// Same 4-stage cp.async pipeline.
// ---------------------------------------------------------------------------
__global__ __launch_bounds__(256, 2) void gemm_kv(
    const float* __restrict__ A,
    const float* __restrict__ Bk, const float* __restrict__ Bv,
    float* __restrict__ Ck, float* __restrict__ Cv,
    const float* __restrict__ gvec)
{
    extern __shared__ unsigned dsm[];
    unsigned* Asb = dsm;
    unsigned* Bsb = dsm + NSTAGE * ABUF;

    const int  N   = HH * ROPE;   // 512
    const int  K   = LAT;         // 128
    const int  lda = LAT;
    const bool isK = blockIdx.x < 4;
    const int  bN  = (blockIdx.x & 3) * 128;
    const int  bM  = blockIdx.y * 128;
    const float* Bsel = isK ? Bk : Bv;
    float*       Csel = isK ? Ck : Cv;

    const int tid  = threadIdx.x;
    const int lane = tid & 31;
    const int warp = tid >> 5;
    const int g    = lane >> 2;
    const int t4   = lane & 3;
    const int wr   = warp >> 2;
    const int wc   = warp & 3;

    const float* Ab = A + (size_t)bM * lda;
    const float* Bb = Bsel + bN;

    const int aRow = tid >> 2;
    const int aCol = (tid & 3) * 4;
    const int bRow = tid >> 5;
    const int bCol = (tid & 31) * 4;

    unsigned sbase;
    asm("{ .reg .u64 t; cvta.to.shared.u64 t, %1; cvt.u32.u64 %0, t; }"
        : "=r"(sbase) : "l"(dsm));
    const unsigned dA0 = sbase + (aRow * ASTRIDE + aCol) * 4;
    const unsigned dA1 = dA0 + 64 * ASTRIDE * 4;
    const unsigned dB0 = sbase + (NSTAGE * ABUF + bRow * BSTRIDE + bCol) * 4;
    const unsigned dB1 = dB0 + 8 * BSTRIDE * 4;

    auto issue = [&](int buf, int k0) {
        const float* ga0 = &Ab[(size_t)aRow * lda + k0 + aCol];
        const float* gb0 = &Bb[(size_t)(k0 + bRow) * N + bCol];
        unsigned offA = buf * ABUF * 4;
        unsigned offB = buf * BBUF * 4;
        CP_ASYNC16(dA0 + offA, ga0);
        CP_ASYNC16(dA1 + offA, ga0 + (size_t)64 * lda);
        CP_ASYNC16(dB0 + offB, gb0);
        CP_ASYNC16(dB1 + offB, gb0 + (size_t)8 * N);
        CP_COMMIT();
    };

    float acc[4][4][4];
    #pragma unroll
    for (int i = 0; i < 4; i++)
        #pragma unroll
        for (int j = 0; j < 4; j++)
            #pragma unroll
            for (int c = 0; c < 4; c++) acc[i][j][c] = 0.f;

    const int nIter = K >> 4;   // 8
    issue(0, 0);
    issue(1, 16);
    issue(2, 32);

    int buf = 0;
    for (int it = 0; it < nIter; it++) {
        CP_WAIT2();
        __syncthreads();
        if (it + 3 < nIter)
            issue((buf + 3) & 3, (it + 3) << 4);

        const unsigned* As = Asb + buf * ABUF;
        const unsigned* Bs = Bsb + buf * BBUF;

        #pragma unroll
        for (int kb = 0; kb < 2; kb++) {
            const int kk = kb * 8;
            unsigned a[4][4], b[4][2];
            #pragma unroll
            for (int mi = 0; mi < 4; mi++) {
                int row = wr * 64 + mi * 16 + g;
                a[mi][0] = As[row * ASTRIDE + kk + t4];
                a[mi][1] = As[(row + 8) * ASTRIDE + kk + t4];
                a[mi][2] = As[row * ASTRIDE + kk + t4 + 4];
                a[mi][3] = As[(row + 8) * ASTRIDE + kk + t4 + 4];
            }
            #pragma unroll
            for (int ni = 0; ni < 4; ni++) {
                int col = wc * 32 + ni * 8 + g;
                b[ni][0] = Bs[(kk + t4) * BSTRIDE + col];
                b[ni][1] = Bs[(kk + t4 + 4) * BSTRIDE + col];
            }
            #pragma unroll
            for (int mi = 0; mi < 4; mi++)
                #pragma unroll
                for (int ni = 0; ni < 4; ni++)
                    mma_tf32(acc[mi][ni], a[mi][0], a[mi][1], a[mi][2], a[mi][3],
                             b[ni][0], b[ni][1]);
        }
        buf = (buf + 1) & 3;
    }

    if (isK) {
        // fused K-RMSNorm over each 32-col head (warp-local)
        #pragma unroll
        for (int mi = 0; mi < 4; mi++) {
            float ss0 = 0.f, ss1 = 0.f;
            #pragma unroll
            for (int ni = 0; ni < 4; ni++) {
                ss0 += acc[mi][ni][0]*acc[mi][ni][0] + acc[mi][ni][1]*acc[mi][ni][1];
                ss1 += acc[mi][ni][2]*acc[mi][ni][2] + acc[mi][ni][3]*acc[mi][ni][3];
            }
            ss0 += __shfl_xor_sync(0xffffffffu, ss0, 1);
            ss0 += __shfl_xor_sync(0xffffffffu, ss0, 2);
            ss1 += __shfl_xor_sync(0xffffffffu, ss1, 1);
            ss1 += __shfl_xor_sync(0xffffffffu, ss1, 2);
            float rinv0 = rsqrtf(ss0 * (1.0f / ROPE) + EPSV);
            float rinv1 = rsqrtf(ss1 * (1.0f / ROPE) + EPSV);
            int row = bM + wr * 64 + mi * 16 + g;
            #pragma unroll
            for (int ni = 0; ni < 4; ni++) {
                int d   = ni * 8 + 2 * t4;
                int col = bN + wc * 32 + d;
                float g0 = gvec[d], g1 = gvec[d + 1];
                *(float2*)&Csel[(size_t)row * N + col] =
                    make_float2(f2tf_f(acc[mi][ni][0] * rinv0 * g0),
                                f2tf_f(acc[mi][ni][1] * rinv0 * g1));
                *(float2*)&Csel[(size_t)(row + 8) * N + col] =
                    make_float2(f2tf_f(acc[mi][ni][2] * rinv1 * g0),
                                f2tf_f(acc[mi][ni][3] * rinv1 * g1));
            }
        }
    } else {
        #pragma unroll
        for (int mi = 0; mi < 4; mi++) {
            #pragma unroll
            for (int ni = 0; ni < 4; ni++) {
                int row = bM + wr * 64 + mi * 16 + g;
                int col = bN + wc * 32 + ni * 8 + 2 * t4;
                *(float2*)&Csel[(size_t)row * N + col] =
                    make_float2(f2tf_f(acc[mi][ni][0]), f2tf_f(acc[mi][ni][1]));
                *(float2*)&Csel[(size_t)(row + 8) * N + col] =
                    make_float2(f2tf_f(acc[mi][ni][2]), f2tf_f(acc[mi][ni][3]));
            }
        }
    }
}

// ---------------------------------------------------------------------------
// kv split-K reduce -> tf32 bits
// ---------------------------------------------------------------------------
__global__ void kv_reduce_kernel(const float* __restrict__ parts,
                                 float* __restrict__ kv)
{
    int i = (blockIdx.x * blockDim.x + threadIdx.x) * 4;
    if (i >= ROWS * LAT) return;
    const int STRIDE = ROWS * LAT;
    float4 s = *(const float4*)&parts[i];
    #pragma unroll
    for (int c = 1; c < KVSPLIT; c++) {
        float4 p = *(const float4*)&parts[c * STRIDE + i];
        s.x += p.x; s.y += p.y; s.z += p.z; s.w += p.w;
    }
    *(float4*)&kv[i] = make_float4(f2tf_f(s.x), f2tf_f(s.y), f2tf_f(s.z), f2tf_f(s.w));
}

// ---------------------------------------------------------------------------
// Pack Wo -> tf32 bits
// ---------------------------------------------------------------------------
__global__ void pack_wo_kernel(const float* __restrict__ Wo, float* __restrict__ WoP)
{
    int idx = blockIdx.x * blockDim.x + threadIdx.x;
    if (idx >= HH * ROPE * DD) return;
    int r = idx >> 10;
    int n = idx & 1023;
    int h = r >> 5;
    int d = r & 31;
    WoP[idx] = f2tf_f(Wo[(size_t)(h * HD + d) * DD + n]);
}

// ---------------------------------------------------------------------------
// Tensor-core flash attention — EXACT R15 version (proven).
// ---------------------------------------------------------------------------
#define ATTN_SMEM ((128*68 + 2*(64*36 + 64*40)) * 4)

__global__ __launch_bounds__(256, 2) void attn_mma_kernel(
    const float* __restrict__ qr, const float* __restrict__ kk_,
    const float* __restrict__ vv, float* __restrict__ att)
{
    extern __shared__ unsigned smemraw[];
    unsigned (*QPs)[68] = (unsigned(*)[68])smemraw;
    unsigned* kvbase = smemraw + 128 * 68;

    const int qt  = (gridDim.x - 1) - blockIdx.x;
    const int bh  = blockIdx.y;
    const int b   = bh >> 4;
    const int h   = bh & 15;
    const int tid = threadIdx.x;
    const int lane = tid & 31;
    const int w    = tid >> 5;
    const int g    = lane >> 2;
    const int t4   = lane & 3;
    const int rbase = b * TT;
    const int W = HH * ROPE;

    for (int f = tid; f < 128 * 8; f += 256) {
        int row = f >> 3, c4 = (f & 7) * 4;
        *(uint4*)&QPs[row][c4] =
            *(const uint4*)&qr[(size_t)(rbase + qt * 128 + row) * W + h * ROPE + c4];
    }
    __syncthreads();

    const int prow = w * 16 + g;
    unsigned aq[4][4];
    #pragma unroll
    for (int ks = 0; ks < 4; ks++) {
        aq[ks][0] = QPs[prow    ][ks * 8 + t4];
        aq[ks][1] = QPs[prow + 8][ks * 8 + t4];
        aq[ks][2] = QPs[prow    ][ks * 8 + t4 + 4];
        aq[ks][3] = QPs[prow + 8][ks * 8 + t4 + 4];
    }

    float m0 = -INFINITY, m1 = -INFINITY, l0 = 0.f, l1 = 0.f;
    float o[4][4];
    #pragma unroll
    for (int ni = 0; ni < 4; ni++)
        #pragma unroll
        for (int c = 0; c < 4; c++) o[ni][c] = 0.f;

    const int pfRow0 = tid >> 3;
    const int pfRow1 = (tid >> 3) + 32;
    const int pfC4   = (tid & 7) * 4;

    const int nkt = 2 * qt + 2;

    uint4 rk0, rk1, rv0, rv1;
    {
        size_t g0 = (size_t)(rbase + pfRow0) * W + h * ROPE + pfC4;
        size_t g1 = (size_t)(rbase + pfRow1) * W + h * ROPE + pfC4;
        rk0 = *(const uint4*)&kk_[g0];
        rk1 = *(const uint4*)&kk_[g1];
        rv0 = *(const uint4*)&vv[g0];
        rv1 = *(const uint4*)&vv[g1];
    }
    {
        unsigned (*Ks0)[36] = (unsigned(*)[36])(kvbase);
        unsigned (*Vs0)[40] = (unsigned(*)[40])(kvbase + 2304);
        *(uint4*)&Ks0[pfRow0][pfC4] = rk0;
        *(uint4*)&Ks0[pfRow1][pfC4] = rk1;
        *(uint4*)&Vs0[pfRow0][pfC4] = rv0;
        *(uint4*)&Vs0[pfRow1][pfC4] = rv1;
    }
    __syncthreads();

    for (int kt = 0; kt < nkt; kt++) {
        const int p = kt & 1;
        unsigned (*Ks)[36] = (unsigned(*)[36])(kvbase + p * 4864);
        unsigned (*Vs)[40] = (unsigned(*)[40])(kvbase + p * 4864 + 2304);

        if (kt + 1 < nkt) {
            size_t g0 = (size_t)(rbase + (kt + 1) * 64 + pfRow0) * W + h * ROPE + pfC4;
            size_t g1 = (size_t)(rbase + (kt + 1) * 64 + pfRow1) * W + h * ROPE + pfC4;
            rk0 = *(const uint4*)&kk_[g0];
            rk1 = *(const uint4*)&kk_[g1];
            rv0 = *(const uint4*)&vv[g0];
            rv1 = *(const uint4*)&vv[g1];
        }

        float s[8][4];
        #pragma unroll
        for (int j = 0; j < 8; j++)
            #pragma unroll
            for (int c = 0; c < 4; c++) s[j][c] = 0.f;

        #pragma unroll
        for (int ks = 0; ks < 4; ks++) {
            #pragma unroll
            for (int j = 0; j < 8; j++) {
                unsigned b0 = Ks[8 * j + g][ks * 8 + t4];
                unsigned b1 = Ks[8 * j + g][ks * 8 + t4 + 4];
                mma_tf32(s[j], aq[ks][0], aq[ks][1], aq[ks][2], aq[ks][3], b0, b1);
            }
        }

        if (kt >= 2 * qt) {
            int off = (kt - 2 * qt) * 64;
            #pragma unroll
            for (int j = 0; j < 8; j++) {
                int cl = off + 8 * j + 2 * t4;
                if (cl     > prow    ) s[j][0] = -INFINITY;
                if (cl + 1 > prow    ) s[j][1] = -INFINITY;
                if (cl     > prow + 8) s[j][2] = -INFINITY;
                if (cl + 1 > prow + 8) s[j][3] = -INFINITY;
            }
        }

        float mx0 = m0, mx1 = m1;
        #pragma unroll
        for (int j = 0; j < 8; j++) {
            mx0 = fmaxf(mx0, fmaxf(s[j][0], s[j][1]));
            mx1 = fmaxf(mx1, fmaxf(s[j][2], s[j][3]));
        }
        mx0 = fmaxf(mx0, __shfl_xor_sync(0xffffffffu, mx0, 1));
        mx0 = fmaxf(mx0, __shfl_xor_sync(0xffffffffu, mx0, 2));
        mx1 = fmaxf(mx1, __shfl_xor_sync(0xffffffffu, mx1, 1));
        mx1 = fmaxf(mx1, __shfl_xor_sync(0xffffffffu, mx1, 2));

        float sc0 = __expf(m0 - mx0);
        float sc1 = __expf(m1 - mx1);
        m0 = mx0; m1 = mx1;

        float ls0 = 0.f, ls1 = 0.f;
        #pragma unroll
        for (int j = 0; j < 8; j++) {
            float p0 = __expf(s[j][0] - m0);
            float p1 = __expf(s[j][1] - m0);
            float p2 = __expf(s[j][2] - m1);
            float p3 = __expf(s[j][3] - m1);
            ls0 += p0 + p1;
            ls1 += p2 + p3;
            QPs[prow    ][8 * j + 2 * t4    ] = f2tf(p0);
            QPs[prow    ][8 * j + 2 * t4 + 1] = f2tf(p1);
            QPs[prow + 8][8 * j + 2 * t4    ] = f2tf(p2);
            QPs[prow + 8][8 * j + 2 * t4 + 1] = f2tf(p3);
        }
        ls0 += __shfl_xor_sync(0xffffffffu, ls0, 1);
        ls0 += __shfl_xor_sync(0xffffffffu, ls0, 2);
        ls1 += __shfl_xor_sync(0xffffffffu, ls1, 1);
        ls1 += __shfl_xor_sync(0xffffffffu, ls1, 2);
        l0 = l0 * sc0 + ls0;
        l1 = l1 * sc1 + ls1;

        #pragma unroll
        for (int ni = 0; ni < 4; ni++) {
            o[ni][0] *= sc0; o[ni][1] *= sc0;
            o[ni][2] *= sc1; o[ni][3] *= sc1;
        }
        __syncwarp();

        #pragma unroll
        for (int ks = 0; ks < 8; ks++) {
            unsigned a0 = QPs[prow    ][ks * 8 + t4];
            unsigned a1 = QPs[prow + 8][ks * 8 + t4];
            unsigned a2 = QPs[prow    ][ks * 8 + t4 + 4];
            unsigned a3 = QPs[prow + 8][ks * 8 + t4 + 4];
            #pragma unroll
            for (int ni = 0; ni < 4; ni++) {
                unsigned b0 = Vs[ks * 8 + t4    ][8 * ni + g];
                unsigned b1 = Vs[ks * 8 + t4 + 4][8 * ni + g];
                mma_tf32(o[ni], a0, a1, a2, a3, b0, b1);
            }
        }
        __syncwarp();

        if (kt + 1 < nkt) {
            const int q = p ^ 1;
            unsigned (*Ksn)[36] = (unsigned(*)[36])(kvbase + q * 4864);
            unsigned (*Vsn)[40] = (unsigned(*)[40])(kvbase + q * 4864 + 2304);
            *(uint4*)&Ksn[pfRow0][pfC4] = rk0;
            *(uint4*)&Ksn[pfRow1][pfC4] = rk1;
            *(uint4*)&Vsn[pfRow0][pfC4] = rv0;
            *(uint4*)&Vsn[pfRow1][pfC4] = rv1;
        }
        __syncthreads();
    }

    float inv0 = 1.0f / l0;
    float inv1 = 1.0f / l1;
    int grow = rbase + qt * 128 + prow;
    float* dst0 = &att[(size_t)grow * W + h * ROPE];
    float* dst1 = dst0 + (size_t)8 * W;
    #pragma unroll
    for (int ni = 0; ni < 4; ni++) {
        int col = 8 * ni + 2 * t4;
        *(float2*)&dst0[col] = make_float2(f2tf_f(o[ni][0] * inv0), f2tf_f(o[ni][1] * inv0));
        *(float2*)&dst1[col] = make_float2(f2tf_f(o[ni][2] * inv1), f2tf_f(o[ni][3] * inv1));
    }
}

// ---------------------------------------------------------------------------
// Launch graph:
//   conv_x (null) -> fork
//   branch A (null): conv_wq -> xWq (MODE 2)
//   branch B (s2):   conv_wkv/wk/wv -> kv split -> reduce -> gemm_kv -> pack_wo
//   join -> attention -> outWo (MODE 0)
// ---------------------------------------------------------------------------
extern "C" void kernel_launch(void* const* d_in, const int* in_sizes, int n_in,
                              void* d_out, int out_size)
{
    const float* x   = (const float*)d_in[0];
    const float* Wq  = (const float*)d_in[1];
    const float* Wkv = (const float*)d_in[2];
    const float* Wk  = (const float*)d_in[3];
    const float* Wv  = (const float*)d_in[4];
    const float* Wo  = (const float*)d_in[5];
    const float* qg  = (const float*)d_in[6];
    const float* kg  = (const float*)d_in[7];
    float* out = (float*)d_out;

    float *pxb, *pqr, *pkv, *pkvp, *pk, *pv, *patt, *pwop, *pwq, *pwkv, *pwk, *pwv;
    cudaGetSymbolAddress((void**)&pxb,  g_xb);
    cudaGetSymbolAddress((void**)&pqr,  g_qr);
    cudaGetSymbolAddress((void**)&pkv,  g_kv);
    cudaGetSymbolAddress((void**)&pkvp, g_kvp);
    cudaGetSymbolAddress((void**)&pk,   g_k);
    cudaGetSymbolAddress((void**)&pv,   g_v);
    cudaGetSymbolAddress((void**)&patt, g_att);
    cudaGetSymbolAddress((void**)&pwop, g_wop);
    cudaGetSymbolAddress((void**)&pwq,  g_wqb);
    cudaGetSymbolAddress((void**)&pwkv, g_wkvb);
    cudaGetSymbolAddress((void**)&pwk,  g_wkb);
    cudaGetSymbolAddress((void**)&pwv,  g_wvb);

    static cudaStream_t s2 = nullptr;
    static cudaEvent_t  evFork = nullptr, evJoin = nullptr;
    if (s2 == nullptr) {
        cudaStreamCreateWithFlags(&s2, cudaStreamNonBlocking);
        cudaEventCreateWithFlags(&evFork, cudaEventDisableTiming);
        cudaEventCreateWithFlags(&evJoin, cudaEventDisableTiming);
        cudaFuncSetAttribute(attn_mma_kernel,
                             cudaFuncAttributeMaxDynamicSharedMemorySize, ATTN_SMEM);
        cudaFuncSetAttribute(gemm_ca<0>, cudaFuncAttributeMaxDynamicSharedMemorySize, GEMM_SMEM);
        cudaFuncSetAttribute(gemm_ca<2>, cudaFuncAttributeMaxDynamicSharedMemorySize, GEMM_SMEM);
        cudaFuncSetAttribute(gemm_ca<3>, cudaFuncAttributeMaxDynamicSharedMemorySize, GEMM_SMEM);
        cudaFuncSetAttribute(gemm_kv,    cudaFuncAttributeMaxDynamicSharedMemorySize, GEMM_SMEM);
    }

    // x -> tf32 bits (needed by both branches)
    conv_tf32<<<(ROWS * DD / 4 + 255) / 256, 256>>>(
        (const float4*)x, (float4*)pxb, ROWS * DD / 4);

    // ---- fork ----
    cudaEventRecord(evFork, 0);
    cudaStreamWaitEvent(s2, evFork, 0);

    // branch B on s2
    conv_tf32<<<(DD * LAT / 4 + 255) / 256, 256, 0, s2>>>(
        (const float4*)Wkv, (float4*)pwkv, DD * LAT / 4);
    conv_tf32<<<(LAT * HH * ROPE / 4 + 255) / 256, 256, 0, s2>>>(
        (const float4*)Wk, (float4*)pwk, LAT * HH * ROPE / 4);
    conv_tf32<<<(LAT * HH * ROPE / 4 + 255) / 256, 256, 0, s2>>>(
        (const float4*)Wv, (float4*)pwv, LAT * HH * ROPE / 4);
    gemm_ca<3><<<dim3(KVSPLIT, ROWS / 128), 256, GEMM_SMEM, s2>>>(
        ROWS, LAT, DD / KVSPLIT, DD, pxb, pwkv, pkvp, nullptr);
    kv_reduce_kernel<<<(ROWS * LAT / 4 + 255) / 256, 256, 0, s2>>>(pkvp, pkv);
    gemm_kv<<<dim3(8, ROWS / 128), 256, GEMM_SMEM, s2>>>(
        pkv, pwk, pwv, pk, pv, kg);
    pack_wo_kernel<<<(HH * ROPE * DD + 255) / 256, 256, 0, s2>>>(Wo, pwop);
    cudaEventRecord(evJoin, s2);

    // branch A on null stream
    conv_tf32<<<(DD * DD / 4 + 255) / 256, 256>>>(
        (const float4*)Wq, (float4*)pwq, DD * DD / 4);
    gemm_ca<2><<<dim3(DD / 128, ROWS / 128), 256, GEMM_SMEM>>>(
        ROWS, DD, DD, DD, pxb, pwq, pqr, qg);

    // ---- join ----
    cudaStreamWaitEvent(0, evJoin, 0);

    // attention
    attn_mma_kernel<<<dim3(TT / 128, BB * HH), 256, ATTN_SMEM>>>(pqr, pk, pv, patt);

    // out = att @ WoP (fp32 output)
    gemm_ca<0><<<dim3(DD / 128, ROWS / 128), 256, GEMM_SMEM>>>(
        ROWS, DD, HH * ROPE, HH * ROPE, patt, pwop, out, nullptr);
}

// round 17
// speedup vs baseline: 1.0349x; 1.0349x over previous
#include <cuda_runtime.h>
#include <cuda_bf16.h>
#include <math.h>

// Problem constants
#define BB   4
#define TT   2048
#define DD   1024
#define HH   16
#define HD   64
#define LAT  128
#define ROPE 32
#define ROWS (BB*TT)          // 8192
#define EPSV 1e-6f
#define KVSPLIT 4

// Scratch (tf32-bit tensors stored as float bit-patterns)
__device__ float g_xb  [ROWS * DD];          // x as tf32 bits
__device__ float g_qr  [ROWS * HH * ROPE];   // tf32 bits, pre-scaled by 0.125*log2(e)
__device__ float g_kv  [ROWS * LAT];         // tf32 bits
__device__ float g_kvp [KVSPLIT * ROWS * LAT];
__device__ float g_k   [ROWS * HH * ROPE];   // tf32 bits
__device__ float g_v   [ROWS * HH * ROPE];   // tf32 bits
__device__ float g_att [ROWS * HH * ROPE];   // tf32 bits
__device__ float g_wop [HH * ROPE * DD];     // tf32 bits
__device__ float g_wqb [DD * DD];            // tf32 bits
__device__ float g_wkvb[DD * LAT];           // tf32 bits
__device__ float g_wkb [LAT * HH * ROPE];    // tf32 bits
__device__ float g_wvb [LAT * HH * ROPE];    // tf32 bits

// ---------------------------------------------------------------------------
__device__ __forceinline__ unsigned f2tf(float f) {
    unsigned u;
    asm("cvt.rna.tf32.f32 %0, %1;" : "=r"(u) : "f"(f));
    return u;
}
__device__ __forceinline__ float f2tf_f(float f) { return __uint_as_float(f2tf(f)); }

__device__ __forceinline__ float ex2f(float x) {   // 2^x, one MUFU op
    float y;
    asm("ex2.approx.f32 %0, %1;" : "=f"(y) : "f"(x));
    return y;
}

__device__ __forceinline__ void mma_tf32(
    float* c, unsigned a0, unsigned a1, unsigned a2, unsigned a3,
    unsigned b0, unsigned b1)
{
    asm volatile(
        "mma.sync.aligned.m16n8k8.row.col.f32.tf32.tf32.f32 "
        "{%0,%1,%2,%3}, {%4,%5,%6,%7}, {%8,%9}, {%0,%1,%2,%3};"
        : "+f"(c[0]), "+f"(c[1]), "+f"(c[2]), "+f"(c[3])
        : "r"(a0), "r"(a1), "r"(a2), "r"(a3), "r"(b0), "r"(b1));
}

#define CP_ASYNC16(dst_u32, src_ptr) \
    asm volatile("cp.async.cg.shared.global [%0], [%1], 16;" \
                 :: "r"(dst_u32), "l"(src_ptr))
#define CP_COMMIT() asm volatile("cp.async.commit_group;")
#define CP_WAIT2()  asm volatile("cp.async.wait_group 2;")

// ---------------------------------------------------------------------------
// elementwise fp32 -> tf32-bits
// ---------------------------------------------------------------------------
__global__ void conv_tf32(const float4* __restrict__ in, float4* __restrict__ out, int n4)
{
    int i = blockIdx.x * blockDim.x + threadIdx.x;
    if (i >= n4) return;
    float4 v = in[i];
    out[i] = make_float4(f2tf_f(v.x), f2tf_f(v.y), f2tf_f(v.z), f2tf_f(v.w));
}

// ---------------------------------------------------------------------------
// 4-stage cp.async pipelined TF32 GEMM. 128x128 CTA tile, BK=16, 256 thr.
// A and B BOTH pre-converted tf32 bits.
// MODE 0: fp32 store
// MODE 2: fused Q-RMSNorm * 0.125*log2e -> packed qr (ld 512), tf32 store
// MODE 3: split-K fp32 partials
// ---------------------------------------------------------------------------
#define ASTRIDE 20
#define BSTRIDE 136
#define ABUF (128*ASTRIDE)
#define BBUF (16*BSTRIDE)
#define NSTAGE 4
#define GEMM_SMEM (NSTAGE*(ABUF + BBUF) * 4)
#define QSCALE 0.18033688011112042f   // 0.125 * log2(e)

template<int MODE>
__global__ __launch_bounds__(256, 2) void gemm_ca(
    int M, int N, int K, int lda,
    const float* __restrict__ A, const float* __restrict__ B,
    float* __restrict__ C, const float* __restrict__ gvec)
{
    extern __shared__ unsigned dsm[];
    unsigned* Asb = dsm;
    unsigned* Bsb = dsm + NSTAGE * ABUF;
    __shared__ float ssbuf[128][4];          // MODE 2 only

    const int tid  = threadIdx.x;
    const int lane = tid & 31;
    const int warp = tid >> 5;
    const int g    = lane >> 2;
    const int t4   = lane & 3;
    const int wr   = warp >> 2;
    const int wc   = warp & 3;

    const int bM = blockIdx.y * 128;
    const int bN = (MODE == 3) ? 0 : blockIdx.x * 128;

    const float* Ap = A;
    const float* Bp = B;
    float*       Cp = C;
    if (MODE == 3) {
        Ap += (size_t)blockIdx.x * K;
        Bp += (size_t)blockIdx.x * K * N;
        Cp += (size_t)blockIdx.x * M * N;
    }

    const float* Ab = Ap + (size_t)bM * lda;
    const float* Bb = Bp + bN;

    const int aRow = tid >> 2;
    const int aCol = (tid & 3) * 4;
    const int bRow = tid >> 5;
    const int bCol = (tid & 31) * 4;

    unsigned sbase;
    asm("{ .reg .u64 t; cvta.to.shared.u64 t, %1; cvt.u32.u64 %0, t; }"
        : "=r"(sbase) : "l"(dsm));
    const unsigned dA0 = sbase + (aRow * ASTRIDE + aCol) * 4;
    const unsigned dA1 = dA0 + 64 * ASTRIDE * 4;
    const unsigned dB0 = sbase + (NSTAGE * ABUF + bRow * BSTRIDE + bCol) * 4;
    const unsigned dB1 = dB0 + 8 * BSTRIDE * 4;

    auto issue = [&](int buf, int k0) {
        const float* ga0 = &Ab[(size_t)aRow * lda + k0 + aCol];
        const float* gb0 = &Bb[(size_t)(k0 + bRow) * N + bCol];
        unsigned offA = buf * ABUF * 4;
        unsigned offB = buf * BBUF * 4;
        CP_ASYNC16(dA0 + offA, ga0);
        CP_ASYNC16(dA1 + offA, ga0 + (size_t)64 * lda);
        CP_ASYNC16(dB0 + offB, gb0);
        CP_ASYNC16(dB1 + offB, gb0 + (size_t)8 * N);
        CP_COMMIT();
    };

    float acc[4][4][4];
    #pragma unroll
    for (int i = 0; i < 4; i++)
        #pragma unroll
        for (int j = 0; j < 4; j++)
            #pragma unroll
            for (int c = 0; c < 4; c++) acc[i][j][c] = 0.f;

    const int nIter = K >> 4;
    issue(0, 0);
    issue(1, 16);
    issue(2, 32);

    int buf = 0;
    for (int it = 0; it < nIter; it++) {
        CP_WAIT2();
        __syncthreads();

        if (it + 3 < nIter)
            issue((buf + 3) & 3, (it + 3) << 4);

        const unsigned* As = Asb + buf * ABUF;
        const unsigned* Bs = Bsb + buf * BBUF;

        #pragma unroll
        for (int kb = 0; kb < 2; kb++) {
            const int kk = kb * 8;
            unsigned a[4][4], b[4][2];
            #pragma unroll
            for (int mi = 0; mi < 4; mi++) {
                int row = wr * 64 + mi * 16 + g;
                a[mi][0] = As[row * ASTRIDE + kk + t4];
                a[mi][1] = As[(row + 8) * ASTRIDE + kk + t4];
                a[mi][2] = As[row * ASTRIDE + kk + t4 + 4];
                a[mi][3] = As[(row + 8) * ASTRIDE + kk + t4 + 4];
            }
            #pragma unroll
            for (int ni = 0; ni < 4; ni++) {
                int col = wc * 32 + ni * 8 + g;
                b[ni][0] = Bs[(kk + t4) * BSTRIDE + col];
                b[ni][1] = Bs[(kk + t4 + 4) * BSTRIDE + col];
            }
            #pragma unroll
            for (int mi = 0; mi < 4; mi++)
                #pragma unroll
                for (int ni = 0; ni < 4; ni++)
                    mma_tf32(acc[mi][ni], a[mi][0], a[mi][1], a[mi][2], a[mi][3],
                             b[ni][0], b[ni][1]);
        }
        buf = (buf + 1) & 3;
    }

    if (MODE == 0 || MODE == 3) {
        #pragma unroll
        for (int mi = 0; mi < 4; mi++) {
            #pragma unroll
            for (int ni = 0; ni < 4; ni++) {
                int row = bM + wr * 64 + mi * 16 + g;
                int col = bN + wc * 32 + ni * 8 + 2 * t4;
                *(float2*)&Cp[(size_t)row * N + col] =
                    make_float2(acc[mi][ni][0], acc[mi][ni][1]);
                *(float2*)&Cp[(size_t)(row + 8) * N + col] =
                    make_float2(acc[mi][ni][2], acc[mi][ni][3]);
            }
        }
    } else {   // MODE 2: Q head = 64 cols = warp pair; smem partial sums
        #pragma unroll
        for (int mi = 0; mi < 4; mi++) {
            float ss0 = 0.f, ss1 = 0.f;
            #pragma unroll
            for (int ni = 0; ni < 4; ni++) {
                ss0 += acc[mi][ni][0]*acc[mi][ni][0] + acc[mi][ni][1]*acc[mi][ni][1];
                ss1 += acc[mi][ni][2]*acc[mi][ni][2] + acc[mi][ni][3]*acc[mi][ni][3];
            }
            ss0 += __shfl_xor_sync(0xffffffffu, ss0, 1);
            ss0 += __shfl_xor_sync(0xffffffffu, ss0, 2);
            ss1 += __shfl_xor_sync(0xffffffffu, ss1, 1);
            ss1 += __shfl_xor_sync(0xffffffffu, ss1, 2);
            if (t4 == 0) {
                int lr = wr * 64 + mi * 16 + g;
                ssbuf[lr][wc]     = ss0;
                ssbuf[lr + 8][wc] = ss1;
            }
        }
        __syncthreads();
        if ((wc & 1) == 0) {
            #pragma unroll
            for (int mi = 0; mi < 4; mi++) {
                int lr = wr * 64 + mi * 16 + g;
                float t0 = ssbuf[lr][wc] + ssbuf[lr][wc ^ 1];
                float t1 = ssbuf[lr + 8][wc] + ssbuf[lr + 8][wc ^ 1];
                float rinv0 = QSCALE * rsqrtf(t0 * (1.0f / HD) + EPSV);
                float rinv1 = QSCALE * rsqrtf(t1 * (1.0f / HD) + EPSV);
                int row = bM + lr;
                #pragma unroll
                for (int ni = 0; ni < 4; ni++) {
                    int d  = ni * 8 + 2 * t4;
                    int cg = bN + wc * 32 + d;
                    int qc = (cg >> 6) * 32 + d;
                    float g0 = gvec[d], g1 = gvec[d + 1];
                    *(float2*)&Cp[(size_t)row * 512 + qc] =
                        make_float2(f2tf_f(acc[mi][ni][0] * rinv0 * g0),
                                    f2tf_f(acc[mi][ni][1] * rinv0 * g1));
                    *(float2*)&Cp[(size_t)(row + 8) * 512 + qc] =
                        make_float2(f2tf_f(acc[mi][ni][2] * rinv1 * g0),
                                    f2tf_f(acc[mi][ni][3] * rinv1 * g1));
                }
            }
        }
    }
}

// ---------------------------------------------------------------------------
// Merged k+v GEMM: grid (8, 64). x-tiles 0..3 -> k (fused K-RMSNorm, tf32),
// x-tiles 4..7 -> v (plain tf32 store). A = kv (tf32 bits), N = 512, K = 128.
// ---------------------------------------------------------------------------
__global__ __launch_bounds__(256, 2) void gemm_kv(
    const float* __restrict__ A,
    const float* __restrict__ Bk, const float* __restrict__ Bv,
    float* __restrict__ Ck, float* __restrict__ Cv,
    const float* __restrict__ gvec)
{
    extern __shared__ unsigned dsm[];
    unsigned* Asb = dsm;
    unsigned* Bsb = dsm + NSTAGE * ABUF;

    const int  N   = HH * ROPE;   // 512
    const int  K   = LAT;         // 128
    const int  lda = LAT;
    const bool isK = blockIdx.x < 4;
    const int  bN  = (blockIdx.x & 3) * 128;
    const int  bM  = blockIdx.y * 128;
    const float* Bsel = isK ? Bk : Bv;
    float*       Csel = isK ? Ck : Cv;

    const int tid  = threadIdx.x;
    const int lane = tid & 31;
    const int warp = tid >> 5;
    const int g    = lane >> 2;
    const int t4   = lane & 3;
    const int wr   = warp >> 2;
    const int wc   = warp & 3;

    const float* Ab = A + (size_t)bM * lda;
    const float* Bb = Bsel + bN;

    const int aRow = tid >> 2;
    const int aCol = (tid & 3) * 4;
    const int bRow = tid >> 5;
    const int bCol = (tid & 31) * 4;

    unsigned sbase;
    asm("{ .reg .u64 t; cvta.to.shared.u64 t, %1; cvt.u32.u64 %0, t; }"
        : "=r"(sbase) : "l"(dsm));
    const unsigned dA0 = sbase + (aRow * ASTRIDE + aCol) * 4;
    const unsigned dA1 = dA0 + 64 * ASTRIDE * 4;
    const unsigned dB0 = sbase + (NSTAGE * ABUF + bRow * BSTRIDE + bCol) * 4;
    const unsigned dB1 = dB0 + 8 * BSTRIDE * 4;

    auto issue = [&](int buf, int k0) {
        const float* ga0 = &Ab[(size_t)aRow * lda + k0 + aCol];
        const float* gb0 = &Bb[(size_t)(k0 + bRow) * N + bCol];
        unsigned offA = buf * ABUF * 4;
        unsigned offB = buf * BBUF * 4;
        CP_ASYNC16(dA0 + offA, ga0);
        CP_ASYNC16(dA1 + offA, ga0 + (size_t)64 * lda);
        CP_ASYNC16(dB0 + offB, gb0);
        CP_ASYNC16(dB1 + offB, gb0 + (size_t)8 * N);
        CP_COMMIT();
    };

    float acc[4][4][4];
    #pragma unroll
    for (int i = 0; i < 4; i++)
        #pragma unroll
        for (int j = 0; j < 4; j++)
            #pragma unroll
            for (int c = 0; c < 4; c++) acc[i][j][c] = 0.f;

    const int nIter = K >> 4;   // 8
    issue(0, 0);
    issue(1, 16);
    issue(2, 32);

    int buf = 0;
    for (int it = 0; it < nIter; it++) {
        CP_WAIT2();
        __syncthreads();
        if (it + 3 < nIter)
            issue((buf + 3) & 3, (it + 3) << 4);

        const unsigned* As = Asb + buf * ABUF;
        const unsigned* Bs = Bsb + buf * BBUF;

        #pragma unroll
        for (int kb = 0; kb < 2; kb++) {
            const int kk = kb * 8;
            unsigned a[4][4], b[4][2];
            #pragma unroll
            for (int mi = 0; mi < 4; mi++) {
                int row = wr * 64 + mi * 16 + g;
                a[mi][0] = As[row * ASTRIDE + kk + t4];
                a[mi][1] = As[(row + 8) * ASTRIDE + kk + t4];
                a[mi][2] = As[row * ASTRIDE + kk + t4 + 4];
                a[mi][3] = As[(row + 8) * ASTRIDE + kk + t4 + 4];
            }
            #pragma unroll
            for (int ni = 0; ni < 4; ni++) {
                int col = wc * 32 + ni * 8 + g;
                b[ni][0] = Bs[(kk + t4) * BSTRIDE + col];
                b[ni][1] = Bs[(kk + t4 + 4) * BSTRIDE + col];
            }
            #pragma unroll
            for (int mi = 0; mi < 4; mi++)
                #pragma unroll
                for (int ni = 0; ni < 4; ni++)
                    mma_tf32(acc[mi][ni], a[mi][0], a[mi][1], a[mi][2], a[mi][3],
                             b[ni][0], b[ni][1]);
        }
        buf = (buf + 1) & 3;
    }

    if (isK) {
        #pragma unroll
        for (int mi = 0; mi < 4; mi++) {
            float ss0 = 0.f, ss1 = 0.f;
            #pragma unroll
            for (int ni = 0; ni < 4; ni++) {
                ss0 += acc[mi][ni][0]*acc[mi][ni][0] + acc[mi][ni][1]*acc[mi][ni][1];
                ss1 += acc[mi][ni][2]*acc[mi][ni][2] + acc[mi][ni][3]*acc[mi][ni][3];
            }
            ss0 += __shfl_xor_sync(0xffffffffu, ss0, 1);
            ss0 += __shfl_xor_sync(0xffffffffu, ss0, 2);
            ss1 += __shfl_xor_sync(0xffffffffu, ss1, 1);
            ss1 += __shfl_xor_sync(0xffffffffu, ss1, 2);
            float rinv0 = rsqrtf(ss0 * (1.0f / ROPE) + EPSV);
            float rinv1 = rsqrtf(ss1 * (1.0f / ROPE) + EPSV);
            int row = bM + wr * 64 + mi * 16 + g;
            #pragma unroll
            for (int ni = 0; ni < 4; ni++) {
                int d   = ni * 8 + 2 * t4;
                int col = bN + wc * 32 + d;
                float g0 = gvec[d], g1 = gvec[d + 1];
                *(float2*)&Csel[(size_t)row * N + col] =
                    make_float2(f2tf_f(acc[mi][ni][0] * rinv0 * g0),
                                f2tf_f(acc[mi][ni][1] * rinv0 * g1));
                *(float2*)&Csel[(size_t)(row + 8) * N + col] =
                    make_float2(f2tf_f(acc[mi][ni][2] * rinv1 * g0),
                                f2tf_f(acc[mi][ni][3] * rinv1 * g1));
            }
        }
    } else {
        #pragma unroll
        for (int mi = 0; mi < 4; mi++) {
            #pragma unroll
            for (int ni = 0; ni < 4; ni++) {
                int row = bM + wr * 64 + mi * 16 + g;
                int col = bN + wc * 32 + ni * 8 + 2 * t4;
                *(float2*)&Csel[(size_t)row * N + col] =
                    make_float2(f2tf_f(acc[mi][ni][0]), f2tf_f(acc[mi][ni][1]));
                *(float2*)&Csel[(size_t)(row + 8) * N + col] =
                    make_float2(f2tf_f(acc[mi][ni][2]), f2tf_f(acc[mi][ni][3]));
            }
        }
    }
}

// ---------------------------------------------------------------------------
// kv split-K reduce -> tf32 bits
// ---------------------------------------------------------------------------
__global__ void kv_reduce_kernel(const float* __restrict__ parts,
                                 float* __restrict__ kv)
{
    int i = (blockIdx.x * blockDim.x + threadIdx.x) * 4;
    if (i >= ROWS * LAT) return;
    const int STRIDE = ROWS * LAT;
    float4 s = *(const float4*)&parts[i];
    #pragma unroll
    for (int c = 1; c < KVSPLIT; c++) {
        float4 p = *(const float4*)&parts[c * STRIDE + i];
        s.x += p.x; s.y += p.y; s.z += p.z; s.w += p.w;
    }
    *(float4*)&kv[i] = make_float4(f2tf_f(s.x), f2tf_f(s.y), f2tf_f(s.z), f2tf_f(s.w));
}

// ---------------------------------------------------------------------------
// Pack Wo -> tf32 bits
// ---------------------------------------------------------------------------
__global__ void pack_wo_kernel(const float* __restrict__ Wo, float* __restrict__ WoP)
{
    int idx = blockIdx.x * blockDim.x + threadIdx.x;
    if (idx >= HH * ROPE * DD) return;
    int r = idx >> 10;
    int n = idx & 1023;
    int h = r >> 5;
    int d = r & 31;
    WoP[idx] = f2tf_f(Wo[(size_t)(h * HD + d) * DD + n]);
}

// ---------------------------------------------------------------------------
// Tensor-core flash attention, BQ=128, 8 warps, K/V double-buffered.
// R17: NO online max — scores are bounded (RMS-normed q,k => |s|<=5.66,
// 2^(s*log2e folded) <= 287, sum <= 6e5: fp32-safe). p = ex2(s) directly
// (log2e pre-folded into qr), l accumulated per-thread, reduced ONCE at end.
// ---------------------------------------------------------------------------
#define ATTN_SMEM ((128*68 + 2*(64*36 + 64*40)) * 4)

__global__ __launch_bounds__(256, 2) void attn_mma_kernel(
    const float* __restrict__ qr, const float* __restrict__ kk_,
    const float* __restrict__ vv, float* __restrict__ att)
{
    extern __shared__ unsigned smemraw[];
    unsigned (*QPs)[68] = (unsigned(*)[68])smemraw;
    unsigned* kvbase = smemraw + 128 * 68;

    const int qt  = (gridDim.x - 1) - blockIdx.x;
    const int bh  = blockIdx.y;
    const int b   = bh >> 4;
    const int h   = bh & 15;
    const int tid = threadIdx.x;
    const int lane = tid & 31;
    const int w    = tid >> 5;
    const int g    = lane >> 2;
    const int t4   = lane & 3;
    const int rbase = b * TT;
    const int W = HH * ROPE;

    for (int f = tid; f < 128 * 8; f += 256) {
        int row = f >> 3, c4 = (f & 7) * 4;
        *(uint4*)&QPs[row][c4] =
            *(const uint4*)&qr[(size_t)(rbase + qt * 128 + row) * W + h * ROPE + c4];
    }
    __syncthreads();

    const int prow = w * 16 + g;
    unsigned aq[4][4];
    #pragma unroll
    for (int ks = 0; ks < 4; ks++) {
        aq[ks][0] = QPs[prow    ][ks * 8 + t4];
        aq[ks][1] = QPs[prow + 8][ks * 8 + t4];
        aq[ks][2] = QPs[prow    ][ks * 8 + t4 + 4];
        aq[ks][3] = QPs[prow + 8][ks * 8 + t4 + 4];
    }

    float l0 = 0.f, l1 = 0.f;          // plain sums (no rescaling needed)
    float o[4][4];
    #pragma unroll
    for (int ni = 0; ni < 4; ni++)
        #pragma unroll
        for (int c = 0; c < 4; c++) o[ni][c] = 0.f;

    const int pfRow0 = tid >> 3;
    const int pfRow1 = (tid >> 3) + 32;
    const int pfC4   = (tid & 7) * 4;

    const int nkt = 2 * qt + 2;

    uint4 rk0, rk1, rv0, rv1;
    {
        size_t g0 = (size_t)(rbase + pfRow0) * W + h * ROPE + pfC4;
        size_t g1 = (size_t)(rbase + pfRow1) * W + h * ROPE + pfC4;
        rk0 = *(const uint4*)&kk_[g0];
        rk1 = *(const uint4*)&kk_[g1];
        rv0 = *(const uint4*)&vv[g0];
        rv1 = *(const uint4*)&vv[g1];
    }
    {
        unsigned (*Ks0)[36] = (unsigned(*)[36])(kvbase);
        unsigned (*Vs0)[40] = (unsigned(*)[40])(kvbase + 2304);
        *(uint4*)&Ks0[pfRow0][pfC4] = rk0;
        *(uint4*)&Ks0[pfRow1][pfC4] = rk1;
        *(uint4*)&Vs0[pfRow0][pfC4] = rv0;
        *(uint4*)&Vs0[pfRow1][pfC4] = rv1;
    }
    __syncthreads();

    for (int kt = 0; kt < nkt; kt++) {
        const int p = kt & 1;
        unsigned (*Ks)[36] = (unsigned(*)[36])(kvbase + p * 4864);
        unsigned (*Vs)[40] = (unsigned(*)[40])(kvbase + p * 4864 + 2304);

        if (kt + 1 < nkt) {
            size_t g0 = (size_t)(rbase + (kt + 1) * 64 + pfRow0) * W + h * ROPE + pfC4;
            size_t g1 = (size_t)(rbase + (kt + 1) * 64 + pfRow1) * W + h * ROPE + pfC4;
            rk0 = *(const uint4*)&kk_[g0];
            rk1 = *(const uint4*)&kk_[g1];
            rv0 = *(const uint4*)&vv[g0];
            rv1 = *(const uint4*)&vv[g1];
        }

        // S = Q @ K^T  (s already in log2 domain: qr pre-scaled by 0.125*log2e)
        float s[8][4];
        #pragma unroll
        for (int j = 0; j < 8; j++)
            #pragma unroll
            for (int c = 0; c < 4; c++) s[j][c] = 0.f;

        #pragma unroll
        for (int ks = 0; ks < 4; ks++) {
            #pragma unroll
            for (int j = 0; j < 8; j++) {
                unsigned b0 = Ks[8 * j + g][ks * 8 + t4];
                unsigned b1 = Ks[8 * j + g][ks * 8 + t4 + 4];
                mma_tf32(s[j], aq[ks][0], aq[ks][1], aq[ks][2], aq[ks][3], b0, b1);
            }
        }

        // causal mask (ex2(-inf) = 0)
        if (kt >= 2 * qt) {
            int off = (kt - 2 * qt) * 64;
            #pragma unroll
            for (int j = 0; j < 8; j++) {
                int cl = off + 8 * j + 2 * t4;
                if (cl     > prow    ) s[j][0] = -INFINITY;
                if (cl + 1 > prow    ) s[j][1] = -INFINITY;
                if (cl     > prow + 8) s[j][2] = -INFINITY;
                if (cl + 1 > prow + 8) s[j][3] = -INFINITY;
            }
        }

        // direct softmax numerator: p = 2^s (bounded <= ~287, fp32-safe)
        #pragma unroll
        for (int j = 0; j < 8; j++) {
            float p0 = ex2f(s[j][0]);
            float p1 = ex2f(s[j][1]);
            float p2 = ex2f(s[j][2]);
            float p3 = ex2f(s[j][3]);
            l0 += p0 + p1;
            l1 += p2 + p3;
            QPs[prow    ][8 * j + 2 * t4    ] = f2tf(p0);
            QPs[prow    ][8 * j + 2 * t4 + 1] = f2tf(p1);
            QPs[prow + 8][8 * j + 2 * t4    ] = f2tf(p2);
            QPs[prow + 8][8 * j + 2 * t4 + 1] = f2tf(p3);
        }
        __syncwarp();

        // O += P @ V
        #pragma unroll
        for (int ks = 0; ks < 8; ks++) {
            unsigned a0 = QPs[prow    ][ks * 8 + t4];
            unsigned a1 = QPs[prow + 8][ks * 8 + t4];
            unsigned a2 = QPs[prow    ][ks * 8 + t4 + 4];
            unsigned a3 = QPs[prow + 8][ks * 8 + t4 + 4];
            #pragma unroll
            for (int ni = 0; ni < 4; ni++) {
                unsigned b0 = Vs[ks * 8 + t4    ][8 * ni + g];
                unsigned b1 = Vs[ks * 8 + t4 + 4][8 * ni + g];
                mma_tf32(o[ni], a0, a1, a2, a3, b0, b1);
            }
        }
        __syncwarp();

        if (kt + 1 < nkt) {
            const int q = p ^ 1;
            unsigned (*Ksn)[36] = (unsigned(*)[36])(kvbase + q * 4864);
            unsigned (*Vsn)[40] = (unsigned(*)[40])(kvbase + q * 4864 + 2304);
            *(uint4*)&Ksn[pfRow0][pfC4] = rk0;
            *(uint4*)&Ksn[pfRow1][pfC4] = rk1;
            *(uint4*)&Vsn[pfRow0][pfC4] = rv0;
            *(uint4*)&Vsn[pfRow1][pfC4] = rv1;
        }
        __syncthreads();
    }

    // single deferred l reduction over the t4 group
    l0 += __shfl_xor_sync(0xffffffffu, l0, 1);
    l0 += __shfl_xor_sync(0xffffffffu, l0, 2);
    l1 += __shfl_xor_sync(0xffffffffu, l1, 1);
    l1 += __shfl_xor_sync(0xffffffffu, l1, 2);

    float inv0 = 1.0f / l0;
    float inv1 = 1.0f / l1;
    int grow = rbase + qt * 128 + prow;
    float* dst0 = &att[(size_t)grow * W + h * ROPE];
    float* dst1 = dst0 + (size_t)8 * W;
    #pragma unroll
    for (int ni = 0; ni < 4; ni++) {
        int col = 8 * ni + 2 * t4;
        *(float2*)&dst0[col] = make_float2(f2tf_f(o[ni][0] * inv0), f2tf_f(o[ni][1] * inv0));
        *(float2*)&dst1[col] = make_float2(f2tf_f(o[ni][2] * inv1), f2tf_f(o[ni][3] * inv1));
    }
}

// ---------------------------------------------------------------------------
// Launch graph:
//   conv_x (null) -> fork
//   branch A (null): conv_wq -> xWq (MODE 2)
//   branch B (s2):   conv_wkv/wk/wv -> kv split -> reduce -> gemm_kv -> pack_wo
//   join -> attention -> outWo (MODE 0)
// ---------------------------------------------------------------------------
extern "C" void kernel_launch(void* const* d_in, const int* in_sizes, int n_in,
                              void* d_out, int out_size)
{
    const float* x   = (const float*)d_in[0];
    const float* Wq  = (const float*)d_in[1];
    const float* Wkv = (const float*)d_in[2];
    const float* Wk  = (const float*)d_in[3];
    const float* Wv  = (const float*)d_in[4];
    const float* Wo  = (const float*)d_in[5];
    const float* qg  = (const float*)d_in[6];
    const float* kg  = (const float*)d_in[7];
    float* out = (float*)d_out;

    float *pxb, *pqr, *pkv, *pkvp, *pk, *pv, *patt, *pwop, *pwq, *pwkv, *pwk, *pwv;
    cudaGetSymbolAddress((void**)&pxb,  g_xb);
    cudaGetSymbolAddress((void**)&pqr,  g_qr);
    cudaGetSymbolAddress((void**)&pkv,  g_kv);
    cudaGetSymbolAddress((void**)&pkvp, g_kvp);
    cudaGetSymbolAddress((void**)&pk,   g_k);
    cudaGetSymbolAddress((void**)&pv,   g_v);
    cudaGetSymbolAddress((void**)&patt, g_att);
    cudaGetSymbolAddress((void**)&pwop, g_wop);
    cudaGetSymbolAddress((void**)&pwq,  g_wqb);
    cudaGetSymbolAddress((void**)&pwkv, g_wkvb);
    cudaGetSymbolAddress((void**)&pwk,  g_wkb);
    cudaGetSymbolAddress((void**)&pwv,  g_wvb);

    static cudaStream_t s2 = nullptr;
    static cudaEvent_t  evFork = nullptr, evJoin = nullptr;
    if (s2 == nullptr) {
        cudaStreamCreateWithFlags(&s2, cudaStreamNonBlocking);
        cudaEventCreateWithFlags(&evFork, cudaEventDisableTiming);
        cudaEventCreateWithFlags(&evJoin, cudaEventDisableTiming);
        cudaFuncSetAttribute(attn_mma_kernel,
                             cudaFuncAttributeMaxDynamicSharedMemorySize, ATTN_SMEM);
        cudaFuncSetAttribute(gemm_ca<0>, cudaFuncAttributeMaxDynamicSharedMemorySize, GEMM_SMEM);
        cudaFuncSetAttribute(gemm_ca<2>, cudaFuncAttributeMaxDynamicSharedMemorySize, GEMM_SMEM);
        cudaFuncSetAttribute(gemm_ca<3>, cudaFuncAttributeMaxDynamicSharedMemorySize, GEMM_SMEM);
        cudaFuncSetAttribute(gemm_kv,    cudaFuncAttributeMaxDynamicSharedMemorySize, GEMM_SMEM);
    }

    // x -> tf32 bits (needed by both branches)
    conv_tf32<<<(ROWS * DD / 4 + 255) / 256, 256>>>(
        (const float4*)x, (float4*)pxb, ROWS * DD / 4);

    // ---- fork ----
    cudaEventRecord(evFork, 0);
    cudaStreamWaitEvent(s2, evFork, 0);

    // branch B on s2
    conv_tf32<<<(DD * LAT / 4 + 255) / 256, 256, 0, s2>>>(
        (const float4*)Wkv, (float4*)pwkv, DD * LAT / 4);
    conv_tf32<<<(LAT * HH * ROPE / 4 + 255) / 256, 256, 0, s2>>>(
        (const float4*)Wk, (float4*)pwk, LAT * HH * ROPE / 4);
    conv_tf32<<<(LAT * HH * ROPE / 4 + 255) / 256, 256, 0, s2>>>(
        (const float4*)Wv, (float4*)pwv, LAT * HH * ROPE / 4);
    gemm_ca<3><<<dim3(KVSPLIT, ROWS / 128), 256, GEMM_SMEM, s2>>>(
        ROWS, LAT, DD / KVSPLIT, DD, pxb, pwkv, pkvp, nullptr);
    kv_reduce_kernel<<<(ROWS * LAT / 4 + 255) / 256, 256, 0, s2>>>(pkvp, pkv);
    gemm_kv<<<dim3(8, ROWS / 128), 256, GEMM_SMEM, s2>>>(
        pkv, pwk, pwv, pk, pv, kg);
    pack_wo_kernel<<<(HH * ROPE * DD + 255) / 256, 256, 0, s2>>>(Wo, pwop);
    cudaEventRecord(evJoin, s2);

    // branch A on null stream
    conv_tf32<<<(DD * DD / 4 + 255) / 256, 256>>>(
        (const float4*)Wq, (float4*)pwq, DD * DD / 4);
    gemm_ca<2><<<dim3(DD / 128, ROWS / 128), 256, GEMM_SMEM>>>(
        ROWS, DD, DD, DD, pxb, pwq, pqr, qg);

    // ---- join ----
    cudaStreamWaitEvent(0, evJoin, 0);

    // attention (no-max softmax)
    attn_mma_kernel<<<dim3(TT / 128, BB * HH), 256, ATTN_SMEM>>>(pqr, pk, pv, patt);

    // out = att @ WoP (fp32 output)
    gemm_ca<0><<<dim3(DD / 128, ROWS / 128), 256, GEMM_SMEM>>>(
        ROWS, DD, HH * ROPE, HH * ROPE, patt, pwop, out, nullptr);
}